// round 2
// baseline (speedup 1.0000x reference)
#include <cuda_runtime.h>
#include <math.h>

#define BB 16
#define CC 64
#define SS 128
#define TT 512
#define TSPLIT 32

// ---------------- scratch (static device memory; no runtime allocs) ----------------
static __device__ float g_xT[(size_t)BB*TT*CC*SS];   // [b][t][c][s]  256 MB
static __device__ float g_Y [(size_t)BB*CC*SS*TT];   // [b][c][s][t]  256 MB
static __device__ float g_P [BB*SS*SS];              // attn logits accumulator
static __device__ float g_A [BB*SS*SS];              // softmaxed attn
static __device__ float g_sx[BB*CC*SS];              // sum over t of x
static __device__ float g_t2[BB*SS];
static __device__ float g_t3[BB*SS];
static __device__ float g_r [BB*SS];
static __device__ float g_M [CC*CC];
static __device__ float g_N [CC*CC];
static __device__ float g_u1[CC];
static __device__ float g_u2[CC];
static __device__ float g_g [CC];
static __device__ float g_dotb[1];

// ---------------- prep: small matrices + zero accumulators ----------------
__global__ void prep_kernel(const float* __restrict__ w11, const float* __restrict__ b11,
                            const float* __restrict__ w12, const float* __restrict__ b12,
                            const float* __restrict__ w13, const float* __restrict__ b13,
                            const float* __restrict__ w14, const float* __restrict__ b14) {
    int tid = threadIdx.x;
    int gtid = blockIdx.x * blockDim.x + tid;
    int nthr = blockDim.x * gridDim.x;
    for (int i = gtid; i < BB*SS*SS; i += nthr) g_P[i] = 0.f;
    for (int i = gtid; i < BB*CC*SS; i += nthr) g_sx[i] = 0.f;
    if (blockIdx.x == 0) {
        for (int idx = tid; idx < CC*CC; idx += blockDim.x) {
            int a = idx / CC, e = idx % CC;
            float m = 0.f, n = 0.f;
            for (int c = 0; c < CC; c++) {
                m += w11[c*CC + a] * w12[c*CC + e];   // M = W11^T W12
                n += w14[a*CC + c] * w13[c*CC + e];   // N = W14 W13
            }
            g_M[idx] = m; g_N[idx] = n;
        }
        for (int a = tid; a < CC; a += blockDim.x) {
            float u1 = 0.f, u2 = 0.f, gg = 0.f;
            for (int c = 0; c < CC; c++) {
                u1 += b11[c] * w12[c*CC + a];
                u2 += w11[c*CC + a] * b12[c];
                gg += w14[a*CC + c] * b13[c];
            }
            g_u1[a] = u1; g_u2[a] = u2; g_g[a] = gg;
        }
        if (tid == 0) {
            float d = 0.f;
            for (int c = 0; c < CC; c++) d += b11[c] * b12[c];
            g_dotb[0] = d * (float)TT;
        }
    }
}

// ---------------- transpose: x[b,c,s,t] -> xT[b,t,c,s]; also sum over t ----------------
__global__ void transpose_kernel(const float* __restrict__ x) {
    __shared__ float tile[32][33];
    int t0 = blockIdx.x * 32;
    int s0 = blockIdx.y * 32;
    int bc = blockIdx.z;
    int b = bc / CC, c = bc % CC;
    const float* src = x + ((size_t)(b*CC + c) * SS) * TT;
    int lt = threadIdx.x & 31;
    int lr = threadIdx.x >> 5;    // 0..7
#pragma unroll
    for (int k = 0; k < 4; k++) {
        int sl = lr + 8*k;
        tile[sl][lt] = src[(size_t)(s0 + sl) * TT + t0 + lt];
    }
    __syncthreads();
    if (threadIdx.x < 32) {
        float sum = 0.f;
#pragma unroll
        for (int k = 0; k < 32; k++) sum += tile[threadIdx.x][k];
        atomicAdd(&g_sx[(b*CC + c)*SS + s0 + threadIdx.x], sum);
    }
#pragma unroll
    for (int k = 0; k < 4; k++) {
        int tl = lr + 8*k;
        g_xT[(((size_t)b*TT + t0 + tl) * CC + c) * SS + s0 + lt] = tile[lt][tl];
    }
}

// ---------------- attn logits: P[b] += sum_t X_t^T (M X_t) ----------------
#define A_SMEM ((2*64*132 + 64*64) * 4)
__global__ void __launch_bounds__(256, 1) attn_acc_kernel() {
    extern __shared__ float sm[];
    float* Xs = sm;                 // [64][132]
    float* Ys = sm + 64*132;        // [64][132]
    float* Ms = sm + 2*64*132;      // [64][64]
    int b = blockIdx.x, split = blockIdx.y;
    int tid = threadIdx.x;
    for (int i = tid; i < CC*CC; i += 256) Ms[i] = g_M[i];

    int ty = tid >> 4, tx = tid & 15;
    int i0 = ty*8, j0 = tx*8;
    int s_me = tid & 127, cbase = (tid >> 7) * 32;

    float p[8][8];
#pragma unroll
    for (int r = 0; r < 8; r++)
#pragma unroll
        for (int q = 0; q < 8; q++) p[r][q] = 0.f;

    for (int t = split; t < TT; t += TSPLIT) {
        const float* src = g_xT + ((size_t)b*TT + t) * CC * SS;
        __syncthreads();
        for (int idx = tid; idx < CC*SS/4; idx += 256) {
            int c = idx >> 5, v = idx & 31;
            float4 val = ((const float4*)src)[c*32 + v];
            *(float4*)&Xs[c*132 + v*4] = val;
        }
        __syncthreads();
        // step1: Y = M X
        {
            float acc[32];
#pragma unroll
            for (int k = 0; k < 32; k++) acc[k] = 0.f;
            for (int cp = 0; cp < CC; cp++) {
                float xv = Xs[cp*132 + s_me];
#pragma unroll
                for (int k = 0; k < 32; k++) acc[k] += Ms[(cbase + k)*CC + cp] * xv;
            }
#pragma unroll
            for (int k = 0; k < 32; k++) Ys[(cbase + k)*132 + s_me] = acc[k];
        }
        __syncthreads();
        // step2: P += X^T Y
        for (int c = 0; c < CC; c++) {
            float xa[8], yb[8];
            *(float4*)&xa[0] = *(float4*)&Xs[c*132 + i0];
            *(float4*)&xa[4] = *(float4*)&Xs[c*132 + i0 + 4];
            *(float4*)&yb[0] = *(float4*)&Ys[c*132 + j0];
            *(float4*)&yb[4] = *(float4*)&Ys[c*132 + j0 + 4];
#pragma unroll
            for (int r = 0; r < 8; r++)
#pragma unroll
                for (int q = 0; q < 8; q++) p[r][q] += xa[r] * yb[q];
        }
    }
    float* Pb = g_P + (size_t)b*SS*SS;
#pragma unroll
    for (int r = 0; r < 8; r++)
#pragma unroll
        for (int q = 0; q < 8; q++)
            atomicAdd(&Pb[(i0 + r)*SS + j0 + q], p[r][q]);
}

// ---------------- bias terms for logits ----------------
__global__ void bias_terms_kernel() {
    int b = blockIdx.x, i = threadIdx.x;  // 128 threads
    float t2 = 0.f, t3 = 0.f;
    for (int a = 0; a < CC; a++) {
        float sv = g_sx[(b*CC + a)*SS + i];
        t2 += g_u2[a] * sv;
        t3 += g_u1[a] * sv;
    }
    g_t2[b*SS + i] = t2;
    g_t3[b*SS + i] = t3;
}

// ---------------- softmax_plus1 + rowsums ----------------
__global__ void softmax_kernel() {
    __shared__ float wm[4], ws[4];
    int bid = blockIdx.x;
    int b = bid >> 7, i = bid & 127;
    int j = threadIdx.x;  // 128 threads
    const float inv_scale = 1.0f / sqrtf((float)(CC * TT));
    float v = (g_P[((size_t)b*SS + i)*SS + j] + g_t2[b*SS + i] + g_t3[b*SS + j] + g_dotb[0]) * inv_scale;
    float m = v;
#pragma unroll
    for (int o = 16; o > 0; o >>= 1) m = fmaxf(m, __shfl_xor_sync(0xffffffff, m, o));
    int w = j >> 5, l = j & 31;
    if (l == 0) wm[w] = m;
    __syncthreads();
    m = fmaxf(fmaxf(wm[0], wm[1]), fmaxf(wm[2], wm[3]));
    float e = expf(v - m);
    float s = e;
#pragma unroll
    for (int o = 16; o > 0; o >>= 1) s += __shfl_xor_sync(0xffffffff, s, o);
    if (l == 0) ws[w] = s;
    __syncthreads();
    s = ws[0] + ws[1] + ws[2] + ws[3];
    float denom = 1.0f + s;
    g_A[((size_t)b*SS + i)*SS + j] = e / denom;
    if (j == 0) g_r[b*SS + i] = s / denom;
}

// ---------------- Y = N (x) : 1x1 conv ----------------
#define C1_SMEM ((64*516 + 64*64) * 4)
__global__ void __launch_bounds__(256, 1) convN_kernel(const float* __restrict__ x) {
    extern __shared__ float sm[];
    float* Xs = sm;             // [64][516]
    float* Ns = sm + 64*516;    // [64][64]
    int s = blockIdx.x, b = blockIdx.y;
    int tid = threadIdx.x;
    for (int i = tid; i < CC*CC; i += 256) Ns[i] = g_N[i];
    const float* src = x + ((size_t)(b*CC) * SS + s) * TT;
    for (int idx = tid; idx < CC*TT/4; idx += 256) {
        int c = idx >> 7, v = idx & 127;
        *(float4*)&Xs[c*516 + v*4] = *(const float4*)&src[(size_t)c*SS*TT + v*4];
    }
    __syncthreads();
    int tx = tid & 63, ty = tid >> 6;   // ty 0..3
    float* dst = g_Y + ((size_t)(b*CC) * SS + s) * TT;
    for (int cc = 0; cc < 2; cc++) {
        int c0 = cc*32 + ty*8;
        float acc[8][8];
#pragma unroll
        for (int r = 0; r < 8; r++)
#pragma unroll
            for (int m2 = 0; m2 < 8; m2++) acc[r][m2] = 0.f;
        for (int cp = 0; cp < CC; cp++) {
            float xv[8];
#pragma unroll
            for (int m2 = 0; m2 < 8; m2++) xv[m2] = Xs[cp*516 + tx + 64*m2];
#pragma unroll
            for (int r = 0; r < 8; r++) {
                float nv = Ns[(c0 + r)*CC + cp];
#pragma unroll
                for (int m2 = 0; m2 < 8; m2++) acc[r][m2] += nv * xv[m2];
            }
        }
#pragma unroll
        for (int r = 0; r < 8; r++)
#pragma unroll
            for (int m2 = 0; m2 < 8; m2++)
                dst[(size_t)(c0 + r)*SS*TT + tx + 64*m2] = acc[r][m2];
    }
}

// ---------------- out = alpha*(A Y + r g + b14) + x ----------------
#define C2_SMEM ((128*132 + 128*132) * 4)
__global__ void __launch_bounds__(256, 1) attn_apply_kernel(const float* __restrict__ x,
                                                            const float* __restrict__ alpha,
                                                            const float* __restrict__ b14,
                                                            float* __restrict__ out) {
    extern __shared__ float sm[];
    float* As  = sm;               // [j][i] (transposed), pitch 132
    float* Ysh = sm + 128*132;     // [j][t], pitch 132
    int tk = blockIdx.x, c = blockIdx.y, b = blockIdx.z;
    int t0 = tk * 128;
    int tid = threadIdx.x;

    const float* Ab = g_A + (size_t)b*SS*SS;
    for (int idx = tid; idx < SS*SS; idx += 256) {
        int i = idx >> 7, j = idx & 127;
        As[j*132 + i] = Ab[idx];
    }
    const float* Yb = g_Y + ((size_t)(b*CC + c) * SS) * TT + t0;
    for (int idx = tid; idx < SS*128/4; idx += 256) {
        int j = idx >> 5, v = idx & 31;
        *(float4*)&Ysh[j*132 + v*4] = *(const float4*)&Yb[(size_t)j*TT + v*4];
    }
    __syncthreads();

    int tx = tid & 15, ty = tid >> 4;
    int i0 = ty * 8;
    float o[8][8];
#pragma unroll
    for (int r = 0; r < 8; r++)
#pragma unroll
        for (int q = 0; q < 8; q++) o[r][q] = 0.f;

    for (int j = 0; j < SS; j++) {
        float av[8], yv[8];
        *(float4*)&av[0] = *(float4*)&As[j*132 + i0];
        *(float4*)&av[4] = *(float4*)&As[j*132 + i0 + 4];
#pragma unroll
        for (int m2 = 0; m2 < 8; m2++) yv[m2] = Ysh[j*132 + tx + 16*m2];
#pragma unroll
        for (int r = 0; r < 8; r++)
#pragma unroll
            for (int q = 0; q < 8; q++) o[r][q] += av[r] * yv[q];
    }

    const float* xp = x     + ((size_t)(b*CC + c) * SS) * TT + t0;
    const float* ap = alpha + ((size_t)c * SS) * TT + t0;
    float*       op = out   + ((size_t)(b*CC + c) * SS) * TT + t0;
    float gc = g_g[c], b14c = b14[c];
#pragma unroll
    for (int r = 0; r < 8; r++) {
        int i = i0 + r;
        float rv = g_r[b*SS + i];
#pragma unroll
        for (int m2 = 0; m2 < 8; m2++) {
            int ttv = tx + 16*m2;
            size_t off = (size_t)i*TT + ttv;
            op[off] = ap[off] * (o[r][m2] + rv*gc + b14c) + xp[off];
        }
    }
}

// ---------------- launcher ----------------
extern "C" void kernel_launch(void* const* d_in, const int* in_sizes, int n_in,
                              void* d_out, int out_size) {
    const float* x    = (const float*)d_in[0];
    const float* w11  = (const float*)d_in[1];
    const float* b11  = (const float*)d_in[2];
    const float* w12  = (const float*)d_in[3];
    const float* b12  = (const float*)d_in[4];
    const float* w13  = (const float*)d_in[5];
    const float* b13  = (const float*)d_in[6];
    const float* w14  = (const float*)d_in[7];
    const float* b14  = (const float*)d_in[8];
    const float* alpha= (const float*)d_in[9];
    float* out = (float*)d_out;

    cudaFuncSetAttribute((const void*)attn_acc_kernel,  cudaFuncAttributeMaxDynamicSharedMemorySize, A_SMEM);
    cudaFuncSetAttribute((const void*)convN_kernel,     cudaFuncAttributeMaxDynamicSharedMemorySize, C1_SMEM);
    cudaFuncSetAttribute((const void*)attn_apply_kernel,cudaFuncAttributeMaxDynamicSharedMemorySize, C2_SMEM);

    prep_kernel<<<256, 256>>>(w11, b11, w12, b12, w13, b13, w14, b14);
    transpose_kernel<<<dim3(TT/32, SS/32, BB*CC), 256>>>(x);
    attn_acc_kernel<<<dim3(BB, TSPLIT), 256, A_SMEM>>>();
    bias_terms_kernel<<<BB, 128>>>();
    softmax_kernel<<<BB*SS, 128>>>();
    convN_kernel<<<dim3(SS, BB), 256, C1_SMEM>>>(x);
    attn_apply_kernel<<<dim3(TT/128, CC, BB), 256, C2_SMEM>>>(x, alpha, b14, out);
}

// round 4
// speedup vs baseline: 2.1124x; 2.1124x over previous
#include <cuda_runtime.h>
#include <cstdint>
#include <math.h>

#define BB 16
#define CC 64
#define SS 128
#define TT 512
#define PCH 68     // smem pitch (floats) for 64-wide tiles
#define PC2 132    // smem pitch (floats) for 128-wide tiles

static __device__ float g_xS[(size_t)BB*TT*SS*CC];   // [b][t][s][c]
static __device__ float g_xM[(size_t)BB*TT*SS*CC];   // [b][t][s][c]  (x mixed by M^T)
static __device__ float g_Y2[(size_t)BB*CC*TT*SS];   // [b][a][t][s]  (x mixed by N^T)
static __device__ float g_P [BB*SS*SS];
static __device__ float g_A [BB*SS*SS];
static __device__ float g_sx[BB*CC*SS];
static __device__ float g_t2[BB*SS];
static __device__ float g_t3[BB*SS];
static __device__ float g_r [BB*SS];
static __device__ float g_M [CC*CC];
static __device__ float g_N [CC*CC];
static __device__ float g_u1[CC];
static __device__ float g_u2[CC];
static __device__ float g_g [CC];
static __device__ float g_dotb[1];

// ---- mma.sync tf32 m16n8k8 ----
#define MMA_TF32(d, a, b0, b1) \
    asm volatile("mma.sync.aligned.m16n8k8.row.col.f32.tf32.tf32.f32 " \
        "{%0,%1,%2,%3}, {%4,%5,%6,%7}, {%8,%9}, {%0,%1,%2,%3};" \
        : "+f"((d)[0]), "+f"((d)[1]), "+f"((d)[2]), "+f"((d)[3]) \
        : "r"(__float_as_uint((a)[0])), "r"(__float_as_uint((a)[1])), \
          "r"(__float_as_uint((a)[2])), "r"(__float_as_uint((a)[3])), \
          "r"(__float_as_uint(b0)), "r"(__float_as_uint(b1)))

__device__ __forceinline__ float to_tf32(float f) {
    uint32_t u;
    asm("cvt.rna.tf32.f32 %0, %1;" : "=r"(u) : "f"(f));
    return __uint_as_float(u);
}
__device__ __forceinline__ float4 to_tf32_4(float4 v) {
    return make_float4(to_tf32(v.x), to_tf32(v.y), to_tf32(v.z), to_tf32(v.w));
}

// ---- prep ----
__global__ void prep_kernel(const float* __restrict__ w11, const float* __restrict__ b11,
                            const float* __restrict__ w12, const float* __restrict__ b12,
                            const float* __restrict__ w13, const float* __restrict__ b13,
                            const float* __restrict__ w14, const float* __restrict__ b14) {
    int tid = threadIdx.x;
    int gtid = blockIdx.x * blockDim.x + tid;
    int nthr = blockDim.x * gridDim.x;
    for (int i = gtid; i < BB*SS*SS; i += nthr) g_P[i] = 0.f;
    for (int i = gtid; i < BB*CC*SS; i += nthr) g_sx[i] = 0.f;
    if (blockIdx.x == 0) {
        for (int idx = tid; idx < CC*CC; idx += blockDim.x) {
            int a = idx / CC, e = idx % CC;
            float m = 0.f, n = 0.f;
            for (int c = 0; c < CC; c++) {
                m += w11[c*CC + a] * w12[c*CC + e];   // M = W11^T W12
                n += w14[a*CC + c] * w13[c*CC + e];   // N = W14 W13
            }
            g_M[idx] = m; g_N[idx] = n;
        }
        for (int a = tid; a < CC; a += blockDim.x) {
            float u1 = 0.f, u2 = 0.f, gg = 0.f;
            for (int c = 0; c < CC; c++) {
                u1 += b11[c] * w12[c*CC + a];
                u2 += w11[c*CC + a] * b12[c];
                gg += w14[a*CC + c] * b13[c];
            }
            g_u1[a] = u1; g_u2[a] = u2; g_g[a] = gg;
        }
        if (tid == 0) {
            float d = 0.f;
            for (int c = 0; c < CC; c++) d += b11[c] * b12[c];
            g_dotb[0] = d * (float)TT;
        }
    }
}

// ---- transpose x[b,c,s,t] -> xS[b,t,s,c]; rowsums over t ----
__global__ void transpose_kernel(const float* __restrict__ x) {
    __shared__ float tile[32][33];
    int t0 = blockIdx.x * 32, c0 = blockIdx.y * 32;
    int bs = blockIdx.z; int b = bs >> 7, s = bs & 127;
    int lt = threadIdx.x & 31, lr = threadIdx.x >> 5;
    const float* src = x + ((size_t)(b*CC + c0)*SS + s)*TT + t0;
#pragma unroll
    for (int k = 0; k < 4; k++) {
        int ci = lr + 8*k;
        tile[ci][lt] = src[(size_t)ci*SS*TT + lt];
    }
    __syncthreads();
    if (threadIdx.x < 32) {
        float sum = 0.f;
#pragma unroll
        for (int j = 0; j < 32; j++) sum += tile[threadIdx.x][j];
        atomicAdd(&g_sx[(b*CC + c0 + threadIdx.x)*SS + s], sum);
    }
    float* dst = g_xS + (((size_t)b*TT + t0)*SS + s)*CC + c0;
#pragma unroll
    for (int k = 0; k < 4; k++) {
        int ti = lr + 8*k;
        dst[(size_t)ti*SS*CC + lt] = tile[lt][ti];
    }
}

// ---- mix: per (b,t): V' = U M^T -> xM[b,t,s,c];  Y2' = U N^T -> Y2[b,a,t,s] ----
#define MIX_SMEM ((128*PCH + 2*64*PCH + 64*PC2) * 4)
__global__ void __launch_bounds__(128, 1) mix_kernel() {
    extern __shared__ float sm[];
    float* Us  = sm;                       // [128][68]
    float* Ms  = sm + 128*PCH;             // [64][68]
    float* Ns  = Ms + 64*PCH;              // [64][68]
    float* Ysm = Ns + 64*PCH;              // [64][132]
    int t = blockIdx.x, b = blockIdx.y;
    int tid = threadIdx.x, lane = tid & 31, w = tid >> 5;
    int gid = lane >> 2, tq = lane & 3;

    for (int i = tid; i < 64*16; i += 128) {
        int r = i >> 4, c4 = (i & 15) * 4;
        *(float4*)&Ms[r*PCH + c4] = to_tf32_4(*(const float4*)&g_M[r*64 + c4]);
        *(float4*)&Ns[r*PCH + c4] = to_tf32_4(*(const float4*)&g_N[r*64 + c4]);
    }
    const float* src = g_xS + ((size_t)(b*TT + t)) * SS * CC;
    for (int i = tid; i < 128*16; i += 128) {
        int r = i >> 4, c4 = (i & 15) * 4;
        *(float4*)&Us[r*PCH + c4] = to_tf32_4(*(const float4*)&src[r*64 + c4]);
    }
    __syncthreads();

    float aV[2][8][4], aN[2][8][4];
#pragma unroll
    for (int mt = 0; mt < 2; mt++)
#pragma unroll
        for (int n = 0; n < 8; n++)
#pragma unroll
            for (int q = 0; q < 4; q++) { aV[mt][n][q] = 0.f; aN[mt][n][q] = 0.f; }

#pragma unroll
    for (int k = 0; k < 8; k++) {
        float af[2][4];
#pragma unroll
        for (int mt = 0; mt < 2; mt++) {
            int base = w*32 + mt*16;
            af[mt][0] = Us[(base + gid    )*PCH + k*8 + tq    ];
            af[mt][1] = Us[(base + gid + 8)*PCH + k*8 + tq    ];
            af[mt][2] = Us[(base + gid    )*PCH + k*8 + tq + 4];
            af[mt][3] = Us[(base + gid + 8)*PCH + k*8 + tq + 4];
        }
#pragma unroll
        for (int n = 0; n < 8; n++) {
            float bm0 = Ms[(n*8 + gid)*PCH + k*8 + tq];
            float bm1 = Ms[(n*8 + gid)*PCH + k*8 + tq + 4];
            float bn0 = Ns[(n*8 + gid)*PCH + k*8 + tq];
            float bn1 = Ns[(n*8 + gid)*PCH + k*8 + tq + 4];
#pragma unroll
            for (int mt = 0; mt < 2; mt++) {
                MMA_TF32(aV[mt][n], af[mt], bm0, bm1);
                MMA_TF32(aN[mt][n], af[mt], bn0, bn1);
            }
        }
    }

    // write V' -> xM[b,t,s,c] (direct, 8B chunks fill 32B sectors)
    float* dstV = g_xM + ((size_t)(b*TT + t)) * SS * CC;
#pragma unroll
    for (int mt = 0; mt < 2; mt++) {
        int row = w*32 + mt*16 + gid;
#pragma unroll
        for (int n = 0; n < 8; n++) {
            int col = n*8 + 2*tq;
            *(float2*)&dstV[row*64 + col]     = make_float2(aV[mt][n][0], aV[mt][n][1]);
            *(float2*)&dstV[(row+8)*64 + col] = make_float2(aV[mt][n][2], aV[mt][n][3]);
        }
    }
    // stage Y2' to smem transposed [a][s], then coalesced to gmem [b,a,t,s]
#pragma unroll
    for (int mt = 0; mt < 2; mt++) {
        int s = w*32 + mt*16 + gid;
#pragma unroll
        for (int n = 0; n < 8; n++) {
            int a0 = n*8 + 2*tq;
            Ysm[ a0   *PC2 + s    ] = aN[mt][n][0];
            Ysm[(a0+1)*PC2 + s    ] = aN[mt][n][1];
            Ysm[ a0   *PC2 + s + 8] = aN[mt][n][2];
            Ysm[(a0+1)*PC2 + s + 8] = aN[mt][n][3];
        }
    }
    __syncthreads();
    for (int i = tid; i < 64*32; i += 128) {
        int a = i >> 5, s4 = (i & 31) * 4;
        float* dst = g_Y2 + (((size_t)b*CC + a)*TT + t)*SS + s4;
        *(float4*)dst = *(float4*)&Ysm[a*PC2 + s4];
    }
}

// ---- stage A: P[b] += sum_t U_t (V'_t)^T ----
#define SA_SMEM ((2*128*PCH) * 4)
__global__ void __launch_bounds__(256, 1) stageA_kernel() {
    extern __shared__ float sm[];
    float* Us = sm;             // [128][68]
    float* Vs = sm + 128*PCH;   // [128][68]
    int b = blockIdx.x, split = blockIdx.y;
    int tid = threadIdx.x, lane = tid & 31, w = tid >> 5;
    int gid = lane >> 2, tq = lane & 3;
    int mw = w & 3, nw = w >> 2;  // m base 32*mw, n base 64*nw

    float acc[2][8][4];
#pragma unroll
    for (int mt = 0; mt < 2; mt++)
#pragma unroll
        for (int n = 0; n < 8; n++)
#pragma unroll
            for (int q = 0; q < 4; q++) acc[mt][n][q] = 0.f;

    for (int it = 0; it < 16; it++) {
        int t = split * 16 + it;
        __syncthreads();
        const float* su = g_xS + ((size_t)(b*TT + t)) * SS * CC;
        const float* sv = g_xM + ((size_t)(b*TT + t)) * SS * CC;
        for (int i = tid; i < 128*16; i += 256) {
            int r = i >> 4, c4 = (i & 15) * 4;
            *(float4*)&Us[r*PCH + c4] = to_tf32_4(*(const float4*)&su[r*64 + c4]);
            *(float4*)&Vs[r*PCH + c4] = to_tf32_4(*(const float4*)&sv[r*64 + c4]);
        }
        __syncthreads();
#pragma unroll
        for (int k = 0; k < 8; k++) {
            float af[2][4];
#pragma unroll
            for (int mt = 0; mt < 2; mt++) {
                int base = mw*32 + mt*16;
                af[mt][0] = Us[(base + gid    )*PCH + k*8 + tq    ];
                af[mt][1] = Us[(base + gid + 8)*PCH + k*8 + tq    ];
                af[mt][2] = Us[(base + gid    )*PCH + k*8 + tq + 4];
                af[mt][3] = Us[(base + gid + 8)*PCH + k*8 + tq + 4];
            }
#pragma unroll
            for (int n = 0; n < 8; n++) {
                int j = nw*64 + n*8;
                float b0 = Vs[(j + gid)*PCH + k*8 + tq];
                float b1 = Vs[(j + gid)*PCH + k*8 + tq + 4];
#pragma unroll
                for (int mt = 0; mt < 2; mt++) MMA_TF32(acc[mt][n], af[mt], b0, b1);
            }
        }
    }
    float* Pb = g_P + (size_t)b*SS*SS;
#pragma unroll
    for (int mt = 0; mt < 2; mt++) {
        int i = mw*32 + mt*16 + gid;
#pragma unroll
        for (int n = 0; n < 8; n++) {
            int j = nw*64 + n*8 + 2*tq;
            atomicAdd(&Pb[i*SS + j],       acc[mt][n][0]);
            atomicAdd(&Pb[i*SS + j + 1],   acc[mt][n][1]);
            atomicAdd(&Pb[(i+8)*SS + j],   acc[mt][n][2]);
            atomicAdd(&Pb[(i+8)*SS + j+1], acc[mt][n][3]);
        }
    }
}

// ---- bias terms ----
__global__ void bias_terms_kernel() {
    int b = blockIdx.x, i = threadIdx.x;
    float t2 = 0.f, t3 = 0.f;
    for (int a = 0; a < CC; a++) {
        float sv = g_sx[(b*CC + a)*SS + i];
        t2 += g_u2[a] * sv;
        t3 += g_u1[a] * sv;
    }
    g_t2[b*SS + i] = t2;
    g_t3[b*SS + i] = t3;
}

// ---- softmax_plus1 + rowsums ----
__global__ void softmax_kernel() {
    __shared__ float wm[4], ws[4];
    int bid = blockIdx.x;
    int b = bid >> 7, i = bid & 127;
    int j = threadIdx.x;
    const float inv_scale = 1.0f / sqrtf((float)(CC * TT));
    float v = (g_P[((size_t)b*SS + i)*SS + j] + g_t2[b*SS + i] + g_t3[b*SS + j] + g_dotb[0]) * inv_scale;
    float m = v;
#pragma unroll
    for (int o = 16; o > 0; o >>= 1) m = fmaxf(m, __shfl_xor_sync(0xffffffff, m, o));
    int w = j >> 5, l = j & 31;
    if (l == 0) wm[w] = m;
    __syncthreads();
    m = fmaxf(fmaxf(wm[0], wm[1]), fmaxf(wm[2], wm[3]));
    float e = expf(v - m);
    float s = e;
#pragma unroll
    for (int o = 16; o > 0; o >>= 1) s += __shfl_xor_sync(0xffffffff, s, o);
    if (l == 0) ws[w] = s;
    __syncthreads();
    s = ws[0] + ws[1] + ws[2] + ws[3];
    float denom = 1.0f + s;
    g_A[((size_t)b*SS + i)*SS + j] = e / denom;
    if (j == 0) g_r[b*SS + i] = s / denom;
}

// ---- stage C: per (b,a,tk): D[i,t'] = attn x Y2^T, fused epilogue ----
#define SC_SMEM ((2*128*PC2) * 4)
__global__ void __launch_bounds__(256, 1) stageC_kernel(const float* __restrict__ x,
                                                        const float* __restrict__ alpha,
                                                        const float* __restrict__ b14,
                                                        float* __restrict__ out) {
    extern __shared__ float sm[];
    float* As = sm;             // attn [i][j], pitch 132
    float* Ys = sm + 128*PC2;   // Y2   [t'][j], pitch 132
    int tk = blockIdx.x, a = blockIdx.y, b = blockIdx.z;
    int t0 = tk * 128;
    int tid = threadIdx.x, lane = tid & 31, w = tid >> 5;
    int gid = lane >> 2, tq = lane & 3;

    const float* Ab = g_A + (size_t)b*SS*SS;
    const float* Yb = g_Y2 + (((size_t)b*CC + a)*TT + t0) * SS;
    for (int i = tid; i < 128*32; i += 256) {
        int r = i >> 5, c4 = (i & 31) * 4;
        *(float4*)&As[r*PC2 + c4] = to_tf32_4(*(const float4*)&Ab[r*128 + c4]);
        *(float4*)&Ys[r*PC2 + c4] = to_tf32_4(*(const float4*)&Yb[(size_t)r*SS + c4]);
    }
    __syncthreads();

    float acc[16][4];
#pragma unroll
    for (int n = 0; n < 16; n++)
#pragma unroll
        for (int q = 0; q < 4; q++) acc[n][q] = 0.f;

#pragma unroll
    for (int k = 0; k < 16; k++) {
        float af[4];
        af[0] = As[(w*16 + gid    )*PC2 + k*8 + tq    ];
        af[1] = As[(w*16 + gid + 8)*PC2 + k*8 + tq    ];
        af[2] = As[(w*16 + gid    )*PC2 + k*8 + tq + 4];
        af[3] = As[(w*16 + gid + 8)*PC2 + k*8 + tq + 4];
#pragma unroll
        for (int n = 0; n < 16; n++) {
            float b0 = Ys[(n*8 + gid)*PC2 + k*8 + tq];
            float b1 = Ys[(n*8 + gid)*PC2 + k*8 + tq + 4];
            MMA_TF32(acc[n], af, b0, b1);
        }
    }

    // epilogue: out[b,a,i,t0+t'] = alpha*(D + r_i*g_a + b14_a) + x
    int i0 = w*16 + gid;
    float ga = g_g[a], ba = b14[a];
    float add0 = g_r[b*SS + i0    ] * ga + ba;
    float add1 = g_r[b*SS + i0 + 8] * ga + ba;
    size_t row0 = (((size_t)b*CC + a)*SS + i0    )*TT + t0;
    size_t row1 = (((size_t)b*CC + a)*SS + i0 + 8)*TT + t0;
    size_t arow0 = ((size_t)a*SS + i0    )*TT + t0;
    size_t arow1 = ((size_t)a*SS + i0 + 8)*TT + t0;
#pragma unroll
    for (int n = 0; n < 16; n++) {
        int tc = n*8 + 2*tq;
        float2 xv0 = *(const float2*)&x[row0 + tc];
        float2 av0 = *(const float2*)&alpha[arow0 + tc];
        float2 o0;
        o0.x = av0.x * (acc[n][0] + add0) + xv0.x;
        o0.y = av0.y * (acc[n][1] + add0) + xv0.y;
        *(float2*)&out[row0 + tc] = o0;
        float2 xv1 = *(const float2*)&x[row1 + tc];
        float2 av1 = *(const float2*)&alpha[arow1 + tc];
        float2 o1;
        o1.x = av1.x * (acc[n][2] + add1) + xv1.x;
        o1.y = av1.y * (acc[n][3] + add1) + xv1.y;
        *(float2*)&out[row1 + tc] = o1;
    }
}

// ---- launcher ----
extern "C" void kernel_launch(void* const* d_in, const int* in_sizes, int n_in,
                              void* d_out, int out_size) {
    const float* x    = (const float*)d_in[0];
    const float* w11  = (const float*)d_in[1];
    const float* b11  = (const float*)d_in[2];
    const float* w12  = (const float*)d_in[3];
    const float* b12  = (const float*)d_in[4];
    const float* w13  = (const float*)d_in[5];
    const float* b13  = (const float*)d_in[6];
    const float* w14  = (const float*)d_in[7];
    const float* b14  = (const float*)d_in[8];
    const float* alpha= (const float*)d_in[9];
    float* out = (float*)d_out;

    cudaFuncSetAttribute((const void*)mix_kernel,    cudaFuncAttributeMaxDynamicSharedMemorySize, MIX_SMEM);
    cudaFuncSetAttribute((const void*)stageA_kernel, cudaFuncAttributeMaxDynamicSharedMemorySize, SA_SMEM);
    cudaFuncSetAttribute((const void*)stageC_kernel, cudaFuncAttributeMaxDynamicSharedMemorySize, SC_SMEM);

    prep_kernel<<<256, 256>>>(w11, b11, w12, b12, w13, b13, w14, b14);
    transpose_kernel<<<dim3(TT/32, CC/32, BB*SS), 256>>>(x);
    mix_kernel<<<dim3(TT, BB), 128, MIX_SMEM>>>();
    stageA_kernel<<<dim3(BB, 32), 256, SA_SMEM>>>();
    bias_terms_kernel<<<BB, 128>>>();
    softmax_kernel<<<BB*SS, 128>>>();
    stageC_kernel<<<dim3(TT/128, CC, BB), 256, SC_SMEM>>>(x, alpha, b14, out);
}

// round 5
// speedup vs baseline: 2.6898x; 1.2733x over previous
#include <cuda_runtime.h>
#include <cstdint>
#include <math.h>

#define BB 16
#define CC 64
#define SS 128
#define TT 512
#define PCH 68     // smem pitch (floats) for 64-wide tiles
#define PC2 132    // smem pitch (floats) for 128-wide tiles

static __device__ float g_xS[(size_t)BB*TT*SS*CC];   // [b][t][s][c]
static __device__ float g_Y2[(size_t)BB*CC*TT*SS];   // [b][a][t][s]  (x mixed by N^T)
static __device__ float g_P [BB*SS*SS];
static __device__ float g_A [BB*SS*SS];
static __device__ float g_sx[BB*CC*SS];
static __device__ float g_t2[BB*SS];
static __device__ float g_t3[BB*SS];
static __device__ float g_r [BB*SS];
static __device__ float g_M [CC*CC];
static __device__ float g_N [CC*CC];
static __device__ float g_u1[CC];
static __device__ float g_u2[CC];
static __device__ float g_g [CC];
static __device__ float g_dotb[1];

// ---- mma.sync tf32 m16n8k8 ----
#define MMA_TF32(d, a, b0, b1) \
    asm volatile("mma.sync.aligned.m16n8k8.row.col.f32.tf32.tf32.f32 " \
        "{%0,%1,%2,%3}, {%4,%5,%6,%7}, {%8,%9}, {%0,%1,%2,%3};" \
        : "+f"((d)[0]), "+f"((d)[1]), "+f"((d)[2]), "+f"((d)[3]) \
        : "r"(__float_as_uint((a)[0])), "r"(__float_as_uint((a)[1])), \
          "r"(__float_as_uint((a)[2])), "r"(__float_as_uint((a)[3])), \
          "r"(__float_as_uint(b0)), "r"(__float_as_uint(b1)))

__device__ __forceinline__ float to_tf32(float f) {
    uint32_t u;
    asm("cvt.rna.tf32.f32 %0, %1;" : "=r"(u) : "f"(f));
    return __uint_as_float(u);
}
__device__ __forceinline__ float4 to_tf32_4(float4 v) {
    return make_float4(to_tf32(v.x), to_tf32(v.y), to_tf32(v.z), to_tf32(v.w));
}

// ---- prep ----
__global__ void prep_kernel(const float* __restrict__ w11, const float* __restrict__ b11,
                            const float* __restrict__ w12, const float* __restrict__ b12,
                            const float* __restrict__ w13, const float* __restrict__ b13,
                            const float* __restrict__ w14, const float* __restrict__ b14) {
    int tid = threadIdx.x;
    int gtid = blockIdx.x * blockDim.x + tid;
    int nthr = blockDim.x * gridDim.x;
    for (int i = gtid; i < BB*SS*SS; i += nthr) g_P[i] = 0.f;
    for (int i = gtid; i < BB*CC*SS; i += nthr) g_sx[i] = 0.f;
    if (blockIdx.x == 0) {
        for (int idx = tid; idx < CC*CC; idx += blockDim.x) {
            int a = idx / CC, e = idx % CC;
            float m = 0.f, n = 0.f;
            for (int c = 0; c < CC; c++) {
                m += w11[c*CC + a] * w12[c*CC + e];   // M = W11^T W12
                n += w14[a*CC + c] * w13[c*CC + e];   // N = W14 W13
            }
            g_M[idx] = m; g_N[idx] = n;
        }
        for (int a = tid; a < CC; a += blockDim.x) {
            float u1 = 0.f, u2 = 0.f, gg = 0.f;
            for (int c = 0; c < CC; c++) {
                u1 += b11[c] * w12[c*CC + a];
                u2 += w11[c*CC + a] * b12[c];
                gg += w14[a*CC + c] * b13[c];
            }
            g_u1[a] = u1; g_u2[a] = u2; g_g[a] = gg;
        }
        if (tid == 0) {
            float d = 0.f;
            for (int c = 0; c < CC; c++) d += b11[c] * b12[c];
            g_dotb[0] = d * (float)TT;
        }
    }
}

// ---- transpose x[b,c,s,t] -> xS[b,t,s,c]; rowsums over t ----
__global__ void transpose_kernel(const float* __restrict__ x) {
    __shared__ float tile[32][33];
    int t0 = blockIdx.x * 32, c0 = blockIdx.y * 32;
    int bs = blockIdx.z; int b = bs >> 7, s = bs & 127;
    int lt = threadIdx.x & 31, lr = threadIdx.x >> 5;
    const float* src = x + ((size_t)(b*CC + c0)*SS + s)*TT + t0;
#pragma unroll
    for (int k = 0; k < 4; k++) {
        int ci = lr + 8*k;
        tile[ci][lt] = src[(size_t)ci*SS*TT + lt];
    }
    __syncthreads();
    if (threadIdx.x < 32) {
        float sum = 0.f;
#pragma unroll
        for (int j = 0; j < 32; j++) sum += tile[threadIdx.x][j];
        atomicAdd(&g_sx[(b*CC + c0 + threadIdx.x)*SS + s], sum);
    }
    float* dst = g_xS + (((size_t)b*TT + t0)*SS + s)*CC + c0;
#pragma unroll
    for (int k = 0; k < 4; k++) {
        int ti = lr + 8*k;
        dst[(size_t)ti*SS*CC + lt] = tile[lt][ti];
    }
}

// ---- fused A: per (b,t): V'=U M^T (smem), Y2'=U N^T (->gmem), P += U V'^T ----
#define FA_SMEM ((2*128*PCH + 2*64*PCH + 64*PC2) * 4)
__global__ void __launch_bounds__(256, 1) fusedA_kernel() {
    extern __shared__ float sm[];
    float* Us  = sm;                 // [128][68]
    float* Vs  = Us + 128*PCH;       // [128][68]
    float* Ms  = Vs + 128*PCH;       // [64][68]
    float* Ns  = Ms + 64*PCH;        // [64][68]
    float* Ysm = Ns + 64*PCH;        // [64][132]
    int b = blockIdx.x, split = blockIdx.y;
    int tid = threadIdx.x, lane = tid & 31, w = tid >> 5;
    int gid = lane >> 2, tq = lane & 3;
    int mw = w & 3, nw = w >> 2;

    for (int i = tid; i < 64*16; i += 256) {
        int r = i >> 4, c4 = (i & 15) * 4;
        *(float4*)&Ms[r*PCH + c4] = to_tf32_4(*(const float4*)&g_M[r*64 + c4]);
        *(float4*)&Ns[r*PCH + c4] = to_tf32_4(*(const float4*)&g_N[r*64 + c4]);
    }

    float pacc[2][8][4];
#pragma unroll
    for (int mt = 0; mt < 2; mt++)
#pragma unroll
        for (int n = 0; n < 8; n++)
#pragma unroll
            for (int q = 0; q < 4; q++) pacc[mt][n][q] = 0.f;

    for (int it = 0; it < 16; it++) {
        int t = split * 16 + it;
        __syncthreads();
        const float* su = g_xS + ((size_t)(b*TT + t)) * SS * CC;
        for (int i = tid; i < 128*16; i += 256) {
            int r = i >> 4, c4 = (i & 15) * 4;
            *(float4*)&Us[r*PCH + c4] = to_tf32_4(*(const float4*)&su[r*64 + c4]);
        }
        __syncthreads();

        // --- mix phase: each warp does 16 m-rows (w*16), full n=64 ---
        float aV[8][4], aN[8][4];
#pragma unroll
        for (int n = 0; n < 8; n++)
#pragma unroll
            for (int q = 0; q < 4; q++) { aV[n][q] = 0.f; aN[n][q] = 0.f; }
#pragma unroll
        for (int k = 0; k < 8; k++) {
            float af[4];
            int base = w*16;
            af[0] = Us[(base + gid    )*PCH + k*8 + tq    ];
            af[1] = Us[(base + gid + 8)*PCH + k*8 + tq    ];
            af[2] = Us[(base + gid    )*PCH + k*8 + tq + 4];
            af[3] = Us[(base + gid + 8)*PCH + k*8 + tq + 4];
#pragma unroll
            for (int n = 0; n < 8; n++) {
                float bm0 = Ms[(n*8 + gid)*PCH + k*8 + tq];
                float bm1 = Ms[(n*8 + gid)*PCH + k*8 + tq + 4];
                float bn0 = Ns[(n*8 + gid)*PCH + k*8 + tq];
                float bn1 = Ns[(n*8 + gid)*PCH + k*8 + tq + 4];
                MMA_TF32(aV[n], af, bm0, bm1);
                MMA_TF32(aN[n], af, bn0, bn1);
            }
        }
        // store V' (tf32) to Vs; stage Y2' transposed [a][s] into Ysm
        {
            int row = w*16 + gid;
#pragma unroll
            for (int n = 0; n < 8; n++) {
                int col = n*8 + 2*tq;
                *(float2*)&Vs[row*PCH + col]     = make_float2(to_tf32(aV[n][0]), to_tf32(aV[n][1]));
                *(float2*)&Vs[(row+8)*PCH + col] = make_float2(to_tf32(aV[n][2]), to_tf32(aV[n][3]));
                int a0 = n*8 + 2*tq;
                Ysm[ a0   *PC2 + row    ] = aN[n][0];
                Ysm[(a0+1)*PC2 + row    ] = aN[n][1];
                Ysm[ a0   *PC2 + row + 8] = aN[n][2];
                Ysm[(a0+1)*PC2 + row + 8] = aN[n][3];
            }
        }
        __syncthreads();

        // --- P accumulation: P += U V'^T ---
#pragma unroll
        for (int k = 0; k < 8; k++) {
            float af[2][4];
#pragma unroll
            for (int mt = 0; mt < 2; mt++) {
                int base = mw*32 + mt*16;
                af[mt][0] = Us[(base + gid    )*PCH + k*8 + tq    ];
                af[mt][1] = Us[(base + gid + 8)*PCH + k*8 + tq    ];
                af[mt][2] = Us[(base + gid    )*PCH + k*8 + tq + 4];
                af[mt][3] = Us[(base + gid + 8)*PCH + k*8 + tq + 4];
            }
#pragma unroll
            for (int n = 0; n < 8; n++) {
                int j = nw*64 + n*8;
                float b0 = Vs[(j + gid)*PCH + k*8 + tq];
                float b1 = Vs[(j + gid)*PCH + k*8 + tq + 4];
#pragma unroll
                for (int mt = 0; mt < 2; mt++) MMA_TF32(pacc[mt][n], af[mt], b0, b1);
            }
        }

        // write Y2' to gmem (coalesced)
        for (int i = tid; i < 64*32; i += 256) {
            int a = i >> 5, s4 = (i & 31) * 4;
            float* dst = g_Y2 + (((size_t)b*CC + a)*TT + t)*SS + s4;
            *(float4*)dst = *(float4*)&Ysm[a*PC2 + s4];
        }
    }

    float* Pb = g_P + (size_t)b*SS*SS;
#pragma unroll
    for (int mt = 0; mt < 2; mt++) {
        int i = mw*32 + mt*16 + gid;
#pragma unroll
        for (int n = 0; n < 8; n++) {
            int j = nw*64 + n*8 + 2*tq;
            atomicAdd(&Pb[i*SS + j],       pacc[mt][n][0]);
            atomicAdd(&Pb[i*SS + j + 1],   pacc[mt][n][1]);
            atomicAdd(&Pb[(i+8)*SS + j],   pacc[mt][n][2]);
            atomicAdd(&Pb[(i+8)*SS + j+1], pacc[mt][n][3]);
        }
    }
}

// ---- bias terms ----
__global__ void bias_terms_kernel() {
    int b = blockIdx.x, i = threadIdx.x;
    float t2 = 0.f, t3 = 0.f;
    for (int a = 0; a < CC; a++) {
        float sv = g_sx[(b*CC + a)*SS + i];
        t2 += g_u2[a] * sv;
        t3 += g_u1[a] * sv;
    }
    g_t2[b*SS + i] = t2;
    g_t3[b*SS + i] = t3;
}

// ---- softmax_plus1 + rowsums ----
__global__ void softmax_kernel() {
    __shared__ float wm[4], ws[4];
    int bid = blockIdx.x;
    int b = bid >> 7, i = bid & 127;
    int j = threadIdx.x;
    const float inv_scale = 1.0f / sqrtf((float)(CC * TT));
    float v = (g_P[((size_t)b*SS + i)*SS + j] + g_t2[b*SS + i] + g_t3[b*SS + j] + g_dotb[0]) * inv_scale;
    float m = v;
#pragma unroll
    for (int o = 16; o > 0; o >>= 1) m = fmaxf(m, __shfl_xor_sync(0xffffffff, m, o));
    int w = j >> 5, l = j & 31;
    if (l == 0) wm[w] = m;
    __syncthreads();
    m = fmaxf(fmaxf(wm[0], wm[1]), fmaxf(wm[2], wm[3]));
    float e = expf(v - m);
    float s = e;
#pragma unroll
    for (int o = 16; o > 0; o >>= 1) s += __shfl_xor_sync(0xffffffff, s, o);
    if (l == 0) ws[w] = s;
    __syncthreads();
    s = ws[0] + ws[1] + ws[2] + ws[3];
    float denom = 1.0f + s;
    g_A[((size_t)b*SS + i)*SS + j] = e / denom;
    if (j == 0) g_r[b*SS + i] = s / denom;
}

// ---- stage C: per (b,a,tk): D[i,t'] = attn x Y2^T, fused epilogue ----
#define SC_SMEM ((2*128*PC2) * 4)
__global__ void __launch_bounds__(256, 1) stageC_kernel(const float* __restrict__ x,
                                                        const float* __restrict__ alpha,
                                                        const float* __restrict__ b14,
                                                        float* __restrict__ out) {
    extern __shared__ float sm[];
    float* As = sm;             // attn [i][j], pitch 132
    float* Ys = sm + 128*PC2;   // Y2   [t'][j], pitch 132
    int tk = blockIdx.x, a = blockIdx.y, b = blockIdx.z;
    int t0 = tk * 128;
    int tid = threadIdx.x, lane = tid & 31, w = tid >> 5;
    int gid = lane >> 2, tq = lane & 3;

    const float* Ab = g_A + (size_t)b*SS*SS;
    const float* Yb = g_Y2 + (((size_t)b*CC + a)*TT + t0) * SS;
    for (int i = tid; i < 128*32; i += 256) {
        int r = i >> 5, c4 = (i & 31) * 4;
        *(float4*)&As[r*PC2 + c4] = to_tf32_4(*(const float4*)&Ab[r*128 + c4]);
        *(float4*)&Ys[r*PC2 + c4] = to_tf32_4(*(const float4*)&Yb[(size_t)r*SS + c4]);
    }
    __syncthreads();

    float acc[16][4];
#pragma unroll
    for (int n = 0; n < 16; n++)
#pragma unroll
        for (int q = 0; q < 4; q++) acc[n][q] = 0.f;

#pragma unroll
    for (int k = 0; k < 16; k++) {
        float af[4];
        af[0] = As[(w*16 + gid    )*PC2 + k*8 + tq    ];
        af[1] = As[(w*16 + gid + 8)*PC2 + k*8 + tq    ];
        af[2] = As[(w*16 + gid    )*PC2 + k*8 + tq + 4];
        af[3] = As[(w*16 + gid + 8)*PC2 + k*8 + tq + 4];
#pragma unroll
        for (int n = 0; n < 16; n++) {
            float b0 = Ys[(n*8 + gid)*PC2 + k*8 + tq];
            float b1 = Ys[(n*8 + gid)*PC2 + k*8 + tq + 4];
            MMA_TF32(acc[n], af, b0, b1);
        }
    }

    int i0 = w*16 + gid;
    float ga = g_g[a], ba = b14[a];
    float add0 = g_r[b*SS + i0    ] * ga + ba;
    float add1 = g_r[b*SS + i0 + 8] * ga + ba;
    size_t row0 = (((size_t)b*CC + a)*SS + i0    )*TT + t0;
    size_t row1 = (((size_t)b*CC + a)*SS + i0 + 8)*TT + t0;
    size_t arow0 = ((size_t)a*SS + i0    )*TT + t0;
    size_t arow1 = ((size_t)a*SS + i0 + 8)*TT + t0;
#pragma unroll
    for (int n = 0; n < 16; n++) {
        int tc = n*8 + 2*tq;
        float2 xv0 = *(const float2*)&x[row0 + tc];
        float2 av0 = *(const float2*)&alpha[arow0 + tc];
        float2 o0;
        o0.x = av0.x * (acc[n][0] + add0) + xv0.x;
        o0.y = av0.y * (acc[n][1] + add0) + xv0.y;
        *(float2*)&out[row0 + tc] = o0;
        float2 xv1 = *(const float2*)&x[row1 + tc];
        float2 av1 = *(const float2*)&alpha[arow1 + tc];
        float2 o1;
        o1.x = av1.x * (acc[n][2] + add1) + xv1.x;
        o1.y = av1.y * (acc[n][3] + add1) + xv1.y;
        *(float2*)&out[row1 + tc] = o1;
    }
}

// ---- launcher ----
extern "C" void kernel_launch(void* const* d_in, const int* in_sizes, int n_in,
                              void* d_out, int out_size) {
    const float* x    = (const float*)d_in[0];
    const float* w11  = (const float*)d_in[1];
    const float* b11  = (const float*)d_in[2];
    const float* w12  = (const float*)d_in[3];
    const float* b12  = (const float*)d_in[4];
    const float* w13  = (const float*)d_in[5];
    const float* b13  = (const float*)d_in[6];
    const float* w14  = (const float*)d_in[7];
    const float* b14  = (const float*)d_in[8];
    const float* alpha= (const float*)d_in[9];
    float* out = (float*)d_out;

    cudaFuncSetAttribute((const void*)fusedA_kernel, cudaFuncAttributeMaxDynamicSharedMemorySize, FA_SMEM);
    cudaFuncSetAttribute((const void*)stageC_kernel, cudaFuncAttributeMaxDynamicSharedMemorySize, SC_SMEM);

    prep_kernel<<<256, 256>>>(w11, b11, w12, b12, w13, b13, w14, b14);
    transpose_kernel<<<dim3(TT/32, CC/32, BB*SS), 256>>>(x);
    fusedA_kernel<<<dim3(BB, 32), 256, FA_SMEM>>>();
    bias_terms_kernel<<<BB, 128>>>();
    softmax_kernel<<<BB*SS, 128>>>();
    stageC_kernel<<<dim3(TT/128, CC, BB), 256, SC_SMEM>>>(x, alpha, b14, out);
}

// round 6
// speedup vs baseline: 2.7724x; 1.0307x over previous
#include <cuda_runtime.h>
#include <cstdint>
#include <math.h>

#define BB 16
#define CC 64
#define SS 128
#define TT 512
#define PCH 68     // smem pitch (floats) for 64-wide tiles
#define PC2 132    // smem pitch (floats) for 128-wide tiles

// interleave permutation within 8-groups: p(k) = (k&3)*2 + (k>>2)
#define P8(k) ((((k) & 3) << 1) | (((k) >> 2) & 1))

static __device__ float g_xS[(size_t)BB*TT*SS*CC];   // [b][t][s][c']  tf32, c-interleaved
static __device__ float g_Y2[(size_t)BB*CC*TT*SS];   // [b][a][t][s']  tf32, s-interleaved
static __device__ float g_P [BB*SS*SS];
static __device__ float g_A [BB*SS*SS];              // tf32, j-interleaved
static __device__ float g_sx[BB*CC*SS];
static __device__ float g_t2[BB*SS];
static __device__ float g_t3[BB*SS];
static __device__ float g_r [BB*SS];
static __device__ float g_M [CC*CC];                 // rows+cols interleaved
static __device__ float g_N [CC*CC];                 // cols interleaved
static __device__ float g_u1[CC];
static __device__ float g_u2[CC];
static __device__ float g_g [CC];
static __device__ float g_dotb[1];

// ---- mma.sync tf32 m16n8k8 ----
#define MMA_TF32(d, a, b0, b1) \
    asm volatile("mma.sync.aligned.m16n8k8.row.col.f32.tf32.tf32.f32 " \
        "{%0,%1,%2,%3}, {%4,%5,%6,%7}, {%8,%9}, {%0,%1,%2,%3};" \
        : "+f"((d)[0]), "+f"((d)[1]), "+f"((d)[2]), "+f"((d)[3]) \
        : "r"(__float_as_uint((a)[0])), "r"(__float_as_uint((a)[1])), \
          "r"(__float_as_uint((a)[2])), "r"(__float_as_uint((a)[3])), \
          "r"(__float_as_uint(b0)), "r"(__float_as_uint(b1)))

__device__ __forceinline__ float to_tf32(float f) {
    uint32_t u;
    asm("cvt.rna.tf32.f32 %0, %1;" : "=r"(u) : "f"(f));
    return __uint_as_float(u);
}

__device__ __forceinline__ uint32_t smem_u32(const void* p) {
    uint32_t a;
    asm("{ .reg .u64 t; cvta.to.shared.u64 t, %1; cvt.u32.u64 %0, t; }" : "=r"(a) : "l"(p));
    return a;
}
#define CP_ASYNC16(dst, src) asm volatile("cp.async.ca.shared.global [%0], [%1], 16;" :: "r"(dst), "l"(src))
#define CP_COMMIT()          asm volatile("cp.async.commit_group;" ::: "memory")
#define CP_WAIT0()           asm volatile("cp.async.wait_group 0;" ::: "memory")

// ---- prep: small matrices (pre-permuted), zero accumulators ----
__global__ void prep_kernel(const float* __restrict__ w11, const float* __restrict__ b11,
                            const float* __restrict__ w12, const float* __restrict__ b12,
                            const float* __restrict__ w13, const float* __restrict__ b13,
                            const float* __restrict__ w14, const float* __restrict__ b14) {
    int tid = threadIdx.x;
    int gtid = blockIdx.x * blockDim.x + tid;
    int nthr = blockDim.x * gridDim.x;
    for (int i = gtid; i < BB*SS*SS; i += nthr) g_P[i] = 0.f;
    for (int i = gtid; i < BB*CC*SS; i += nthr) g_sx[i] = 0.f;
    if (blockIdx.x == 0) {
        for (int idx = tid; idx < CC*CC; idx += blockDim.x) {
            int a = idx / CC, e = idx % CC;
            float m = 0.f, n = 0.f;
            for (int c = 0; c < CC; c++) {
                m += w11[c*CC + a] * w12[c*CC + e];   // M = W11^T W12
                n += w14[a*CC + c] * w13[c*CC + e];   // N = W14 W13
            }
            int qa = (a & ~7) | P8(a & 7);
            int qe = (e & ~7) | P8(e & 7);
            g_M[qa*CC + qe] = to_tf32(m);   // rows permuted -> Vs lands interleaved
            g_N[a*CC + qe]  = to_tf32(n);   // cols permuted only
        }
        for (int a = tid; a < CC; a += blockDim.x) {
            float u1 = 0.f, u2 = 0.f, gg = 0.f;
            for (int c = 0; c < CC; c++) {
                u1 += b11[c] * w12[c*CC + a];
                u2 += w11[c*CC + a] * b12[c];
                gg += w14[a*CC + c] * b13[c];
            }
            g_u1[a] = u1; g_u2[a] = u2; g_g[a] = gg;
        }
        if (tid == 0) {
            float d = 0.f;
            for (int c = 0; c < CC; c++) d += b11[c] * b12[c];
            g_dotb[0] = d * (float)TT;
        }
    }
}

// ---- transpose x[b,c,s,t] -> xS[b,t,s,c'] (tf32, c interleaved); rowsums over t ----
__global__ void transpose_kernel(const float* __restrict__ x) {
    __shared__ float tile[32][33];
    int t0 = blockIdx.x * 32, c0 = blockIdx.y * 32;
    int bs = blockIdx.z; int b = bs >> 7, s = bs & 127;
    int lt = threadIdx.x & 31, lr = threadIdx.x >> 5;
    const float* src = x + ((size_t)(b*CC + c0)*SS + s)*TT + t0;
#pragma unroll
    for (int k = 0; k < 4; k++) {
        int ci = lr + 8*k;
        tile[ci][lt] = src[(size_t)ci*SS*TT + lt];
    }
    __syncthreads();
    if (threadIdx.x < 32) {
        float sum = 0.f;
#pragma unroll
        for (int j = 0; j < 32; j++) sum += tile[threadIdx.x][j];
        atomicAdd(&g_sx[(b*CC + c0 + threadIdx.x)*SS + s], sum);
    }
    int plt = (lt & ~7) | P8(lt & 7);
    float* dst = g_xS + (((size_t)b*TT + t0)*SS + s)*CC + c0;
#pragma unroll
    for (int k = 0; k < 4; k++) {
        int ti = lr + 8*k;
        dst[(size_t)ti*SS*CC + plt] = to_tf32(tile[lt][ti]);
    }
}

// ---- fused A: per (b,t): V'=U M^T (smem), Y2'=U N^T (->gmem), P += U V'^T ----
#define FA_SMEM ((3*128*PCH + 2*64*PCH + 64*PC2) * 4)
__global__ void __launch_bounds__(256, 1) fusedA_kernel() {
    extern __shared__ float sm[];
    float* Us0 = sm;                  // [128][68] double-buffered
    float* Us1 = Us0 + 128*PCH;
    float* Vs  = Us1 + 128*PCH;       // [128][68]
    float* Ms  = Vs + 128*PCH;        // [64][68]
    float* Ns  = Ms + 64*PCH;         // [64][68]
    float* Ysm = Ns + 64*PCH;         // [64][132]
    uint32_t us_addr[2] = { smem_u32(Us0), smem_u32(Us1) };

    int b = blockIdx.x, split = blockIdx.y;
    int tid = threadIdx.x, lane = tid & 31, w = tid >> 5;
    int gid = lane >> 2, tq = lane & 3;
    int mw = w & 3, nw = w >> 2;

    for (int i = tid; i < 64*16; i += 256) {
        int r = i >> 4, c4 = (i & 15) * 4;
        *(float4*)&Ms[r*PCH + c4] = *(const float4*)&g_M[r*64 + c4];
        *(float4*)&Ns[r*PCH + c4] = *(const float4*)&g_N[r*64 + c4];
    }

    // prefetch U[0]
    {
        const float* su = g_xS + ((size_t)(b*TT + split*16)) * SS * CC;
        for (int i = tid; i < 128*16; i += 256) {
            int r = i >> 4, c4 = (i & 15) * 4;
            CP_ASYNC16(us_addr[0] + (uint32_t)(r*PCH + c4)*4, su + r*64 + c4);
        }
        CP_COMMIT();
    }

    float pacc[2][8][4];
#pragma unroll
    for (int mt = 0; mt < 2; mt++)
#pragma unroll
        for (int n = 0; n < 8; n++)
#pragma unroll
            for (int q = 0; q < 4; q++) pacc[mt][n][q] = 0.f;

    for (int it = 0; it < 16; it++) {
        float* Us = (it & 1) ? Us1 : Us0;
        CP_WAIT0();
        __syncthreads();
        if (it + 1 < 16) {
            const float* su = g_xS + ((size_t)(b*TT + split*16 + it + 1)) * SS * CC;
            uint32_t ua = us_addr[(it + 1) & 1];
            for (int i = tid; i < 128*16; i += 256) {
                int r = i >> 4, c4 = (i & 15) * 4;
                CP_ASYNC16(ua + (uint32_t)(r*PCH + c4)*4, su + r*64 + c4);
            }
            CP_COMMIT();
        }

        // --- mix phase: each warp does 16 m-rows (w*16), full n=64 ---
        float aV[8][4], aN[8][4];
#pragma unroll
        for (int n = 0; n < 8; n++)
#pragma unroll
            for (int q = 0; q < 4; q++) { aV[n][q] = 0.f; aN[n][q] = 0.f; }
#pragma unroll
        for (int k = 0; k < 8; k++) {
            float af[4];
            int base = w*16;
            float2 x0 = *(float2*)&Us[(base + gid    )*PCH + k*8 + 2*tq];
            float2 x1 = *(float2*)&Us[(base + gid + 8)*PCH + k*8 + 2*tq];
            af[0] = x0.x; af[2] = x0.y; af[1] = x1.x; af[3] = x1.y;
#pragma unroll
            for (int n = 0; n < 8; n++) {
                float2 bm = *(float2*)&Ms[(n*8 + gid)*PCH + k*8 + 2*tq];
                float2 bn = *(float2*)&Ns[(n*8 + gid)*PCH + k*8 + 2*tq];
                MMA_TF32(aV[n], af, bm.x, bm.y);
                MMA_TF32(aN[n], af, bn.x, bn.y);
            }
        }
        // store V' (tf32; cols are interleaved-a because M rows were permuted)
        // stage Y2' transposed [a][s'] with s interleaved
        {
            int row = w*16 + gid;
            int rp  = (row & ~7) | P8(row & 7);
#pragma unroll
            for (int n = 0; n < 8; n++) {
                int col = n*8 + 2*tq;
                *(float2*)&Vs[row*PCH + col]     = make_float2(to_tf32(aV[n][0]), to_tf32(aV[n][1]));
                *(float2*)&Vs[(row+8)*PCH + col] = make_float2(to_tf32(aV[n][2]), to_tf32(aV[n][3]));
                int a0 = n*8 + 2*tq;
                Ysm[ a0   *PC2 + rp    ] = to_tf32(aN[n][0]);
                Ysm[(a0+1)*PC2 + rp    ] = to_tf32(aN[n][1]);
                Ysm[ a0   *PC2 + rp + 8] = to_tf32(aN[n][2]);
                Ysm[(a0+1)*PC2 + rp + 8] = to_tf32(aN[n][3]);
            }
        }
        __syncthreads();

        // --- P accumulation: P += U V'^T ---
#pragma unroll
        for (int k = 0; k < 8; k++) {
            float af[2][4];
#pragma unroll
            for (int mt = 0; mt < 2; mt++) {
                int base = mw*32 + mt*16;
                float2 x0 = *(float2*)&Us[(base + gid    )*PCH + k*8 + 2*tq];
                float2 x1 = *(float2*)&Us[(base + gid + 8)*PCH + k*8 + 2*tq];
                af[mt][0] = x0.x; af[mt][2] = x0.y; af[mt][1] = x1.x; af[mt][3] = x1.y;
            }
#pragma unroll
            for (int n = 0; n < 8; n++) {
                int j = nw*64 + n*8;
                float2 bv = *(float2*)&Vs[(j + gid)*PCH + k*8 + 2*tq];
#pragma unroll
                for (int mt = 0; mt < 2; mt++) MMA_TF32(pacc[mt][n], af[mt], bv.x, bv.y);
            }
        }

        // write Y2' to gmem (coalesced; s-dim stays interleaved in gmem)
        int t = split*16 + it;
        for (int i = tid; i < 64*32; i += 256) {
            int a = i >> 5, s4 = (i & 31) * 4;
            float* dst = g_Y2 + (((size_t)b*CC + a)*TT + t)*SS + s4;
            *(float4*)dst = *(float4*)&Ysm[a*PC2 + s4];
        }
    }

    float* Pb = g_P + (size_t)b*SS*SS;
#pragma unroll
    for (int mt = 0; mt < 2; mt++) {
        int i = mw*32 + mt*16 + gid;
#pragma unroll
        for (int n = 0; n < 8; n++) {
            int j = nw*64 + n*8 + 2*tq;
            atomicAdd(&Pb[i*SS + j],       pacc[mt][n][0]);
            atomicAdd(&Pb[i*SS + j + 1],   pacc[mt][n][1]);
            atomicAdd(&Pb[(i+8)*SS + j],   pacc[mt][n][2]);
            atomicAdd(&Pb[(i+8)*SS + j+1], pacc[mt][n][3]);
        }
    }
}

// ---- bias terms ----
__global__ void bias_terms_kernel() {
    int b = blockIdx.x, i = threadIdx.x;
    float t2 = 0.f, t3 = 0.f;
    for (int a = 0; a < CC; a++) {
        float sv = g_sx[(b*CC + a)*SS + i];
        t2 += g_u2[a] * sv;
        t3 += g_u1[a] * sv;
    }
    g_t2[b*SS + i] = t2;
    g_t3[b*SS + i] = t3;
}

// ---- softmax_plus1 + rowsums; writes A tf32 with interleaved j ----
__global__ void softmax_kernel() {
    __shared__ float wm[4], ws[4];
    int bid = blockIdx.x;
    int b = bid >> 7, i = bid & 127;
    int j = threadIdx.x;
    const float inv_scale = 1.0f / sqrtf((float)(CC * TT));
    float v = (g_P[((size_t)b*SS + i)*SS + j] + g_t2[b*SS + i] + g_t3[b*SS + j] + g_dotb[0]) * inv_scale;
    float m = v;
#pragma unroll
    for (int o = 16; o > 0; o >>= 1) m = fmaxf(m, __shfl_xor_sync(0xffffffff, m, o));
    int w = j >> 5, l = j & 31;
    if (l == 0) wm[w] = m;
    __syncthreads();
    m = fmaxf(fmaxf(wm[0], wm[1]), fmaxf(wm[2], wm[3]));
    float e = expf(v - m);
    float s = e;
#pragma unroll
    for (int o = 16; o > 0; o >>= 1) s += __shfl_xor_sync(0xffffffff, s, o);
    if (l == 0) ws[w] = s;
    __syncthreads();
    s = ws[0] + ws[1] + ws[2] + ws[3];
    float denom = 1.0f + s;
    int jp = (j & ~7) | P8(j & 7);
    g_A[((size_t)b*SS + i)*SS + jp] = to_tf32(e / denom);
    if (j == 0) g_r[b*SS + i] = s / denom;
}

// ---- stage C: per (b,a,tk64): D[i,t'] = attn x Y2^T, fused epilogue ----
#define SC_SMEM ((128*PC2 + 64*PC2) * 4)
__global__ void __launch_bounds__(256, 2) stageC_kernel(const float* __restrict__ x,
                                                        const float* __restrict__ alpha,
                                                        const float* __restrict__ b14,
                                                        float* __restrict__ out) {
    extern __shared__ float sm[];
    float* As = sm;             // attn [i][j'], pitch 132 (pre-rounded, j interleaved)
    float* Ys = sm + 128*PC2;   // Y2   [t'][j'], pitch 132 (pre-rounded, j interleaved)
    uint32_t as_addr = smem_u32(As), ys_addr = smem_u32(Ys);
    int tk = blockIdx.x, a = blockIdx.y, b = blockIdx.z;
    int t0 = tk * 64;
    int tid = threadIdx.x, lane = tid & 31, w = tid >> 5;
    int gid = lane >> 2, tq = lane & 3;

    const float* Ab = g_A + (size_t)b*SS*SS;
    const float* Yb = g_Y2 + (((size_t)b*CC + a)*TT + t0) * SS;
    for (int i = tid; i < 128*32; i += 256) {
        int r = i >> 5, c4 = (i & 31) * 4;
        CP_ASYNC16(as_addr + (uint32_t)(r*PC2 + c4)*4, Ab + r*128 + c4);
    }
    for (int i = tid; i < 64*32; i += 256) {
        int r = i >> 5, c4 = (i & 31) * 4;
        CP_ASYNC16(ys_addr + (uint32_t)(r*PC2 + c4)*4, Yb + (size_t)r*SS + c4);
    }
    CP_COMMIT();
    CP_WAIT0();
    __syncthreads();

    float acc[8][4];
#pragma unroll
    for (int n = 0; n < 8; n++)
#pragma unroll
        for (int q = 0; q < 4; q++) acc[n][q] = 0.f;

#pragma unroll
    for (int k = 0; k < 16; k++) {
        float af[4];
        float2 x0 = *(float2*)&As[(w*16 + gid    )*PC2 + k*8 + 2*tq];
        float2 x1 = *(float2*)&As[(w*16 + gid + 8)*PC2 + k*8 + 2*tq];
        af[0] = x0.x; af[2] = x0.y; af[1] = x1.x; af[3] = x1.y;
#pragma unroll
        for (int n = 0; n < 8; n++) {
            float2 bv = *(float2*)&Ys[(n*8 + gid)*PC2 + k*8 + 2*tq];
            MMA_TF32(acc[n], af, bv.x, bv.y);
        }
    }

    int i0 = w*16 + gid;
    float ga = g_g[a], ba = b14[a];
    float add0 = g_r[b*SS + i0    ] * ga + ba;
    float add1 = g_r[b*SS + i0 + 8] * ga + ba;
    size_t row0 = (((size_t)b*CC + a)*SS + i0    )*TT + t0;
    size_t row1 = (((size_t)b*CC + a)*SS + i0 + 8)*TT + t0;
    size_t arow0 = ((size_t)a*SS + i0    )*TT + t0;
    size_t arow1 = ((size_t)a*SS + i0 + 8)*TT + t0;
#pragma unroll
    for (int n = 0; n < 8; n++) {
        int tc = n*8 + 2*tq;
        float2 xv0 = *(const float2*)&x[row0 + tc];
        float2 av0 = *(const float2*)&alpha[arow0 + tc];
        float2 o0;
        o0.x = av0.x * (acc[n][0] + add0) + xv0.x;
        o0.y = av0.y * (acc[n][1] + add0) + xv0.y;
        *(float2*)&out[row0 + tc] = o0;
        float2 xv1 = *(const float2*)&x[row1 + tc];
        float2 av1 = *(const float2*)&alpha[arow1 + tc];
        float2 o1;
        o1.x = av1.x * (acc[n][2] + add1) + xv1.x;
        o1.y = av1.y * (acc[n][3] + add1) + xv1.y;
        *(float2*)&out[row1 + tc] = o1;
    }
}

// ---- launcher ----
extern "C" void kernel_launch(void* const* d_in, const int* in_sizes, int n_in,
                              void* d_out, int out_size) {
    const float* x    = (const float*)d_in[0];
    const float* w11  = (const float*)d_in[1];
    const float* b11  = (const float*)d_in[2];
    const float* w12  = (const float*)d_in[3];
    const float* b12  = (const float*)d_in[4];
    const float* w13  = (const float*)d_in[5];
    const float* b13  = (const float*)d_in[6];
    const float* w14  = (const float*)d_in[7];
    const float* b14  = (const float*)d_in[8];
    const float* alpha= (const float*)d_in[9];
    float* out = (float*)d_out;

    cudaFuncSetAttribute((const void*)fusedA_kernel, cudaFuncAttributeMaxDynamicSharedMemorySize, FA_SMEM);
    cudaFuncSetAttribute((const void*)stageC_kernel, cudaFuncAttributeMaxDynamicSharedMemorySize, SC_SMEM);

    prep_kernel<<<256, 256>>>(w11, b11, w12, b12, w13, b13, w14, b14);
    transpose_kernel<<<dim3(TT/32, CC/32, BB*SS), 256>>>(x);
    fusedA_kernel<<<dim3(BB, 32), 256, FA_SMEM>>>();
    bias_terms_kernel<<<BB, 128>>>();
    softmax_kernel<<<BB*SS, 128>>>();
    stageC_kernel<<<dim3(TT/64, CC, BB), 256, SC_SMEM>>>(x, alpha, b14, out);
}